// round 5
// baseline (speedup 1.0000x reference)
#include <cuda_runtime.h>

#define B_TOT    131072
#define DIN      128
#define SDIM     64
#define ROWS     64
#define NTHREADS 256
#define HALF_LOG2PI 0.9189385332046727f

// smem float offsets
#define YS_OFF   0                        // 128*65 = 8320 floats
#define ST2_OFF  (DIN*65)                 // 32*65 = 2080
#define EPS2_OFF (ST2_OFF + 32*65)        // 2080
#define LP_OFF   (EPS2_OFF + 32*65)       // 64
#define MISS_BYTE_OFF ((LP_OFF + 64)*4)
#define SMEM_BYTES (MISS_BYTE_OFF + 64*68)   // 54528 B -> 3 CTAs/SM, L1D ~64KB

typedef unsigned long long u64;

// Repacked weights (prep kernel)
__device__ float4 g_Wc2[DIN*16*4];   // [d][fpair][8 f32x2: o0..o6,pad]
__device__ float2 g_Wr2[DIN*32];     // [d][f] (mean_w, logvar_w)
__device__ float  g_Wzt[SDIM*64];    // [d][z]
__device__ float2 g_bc2[16*8];       // cat bias pairs

__global__ void repack_kernel(const float* __restrict__ Wc,
                              const float* __restrict__ Wr,
                              const float* __restrict__ Wz,
                              const float* __restrict__ bc) {
    int idx = blockIdx.x*blockDim.x + threadIdx.x;
    if (idx < DIN*32) {
        int d = idx >> 5, f = idx & 31;
        g_Wr2[d*32 + f] = make_float2(Wr[(f*DIN + d)*2], Wr[(f*DIN + d)*2 + 1]);
        int dz = idx >> 6, z = idx & 63;
        g_Wzt[dz*64 + z] = Wz[z*SDIM + dz];
    }
    if (idx < DIN*16) {
        int d = idx >> 4, fp = idx & 15;
        const float* s0 = Wc + ((2*fp)*DIN + d)*7;
        const float* s1 = Wc + ((2*fp+1)*DIN + d)*7;
        float4* dst = &g_Wc2[(d*16 + fp)*4];
        dst[0] = make_float4(s0[0], s1[0], s0[1], s1[1]);
        dst[1] = make_float4(s0[2], s1[2], s0[3], s1[3]);
        dst[2] = make_float4(s0[4], s1[4], s0[5], s1[5]);
        dst[3] = make_float4(s0[6], s1[6], 0.0f, 0.0f);
    }
    if (idx < 128) {
        int fp = idx >> 3, o = idx & 7;
        g_bc2[idx] = (o < 7) ? make_float2(bc[(2*fp)*7 + o], bc[(2*fp+1)*7 + o])
                             : make_float2(0.0f, 0.0f);
    }
}

__device__ __forceinline__ u64 pack2(float lo, float hi) {
    u64 r; asm("mov.b64 %0, {%1, %2};" : "=l"(r) : "f"(lo), "f"(hi)); return r;
}
__device__ __forceinline__ float2 unpack2(u64 v) {
    float2 r; asm("mov.b64 {%0, %1}, %2;" : "=f"(r.x), "=f"(r.y) : "l"(v)); return r;
}
__device__ __forceinline__ void fma2(u64 &d, u64 a, u64 b) {
    asm("fma.rn.f32x2 %0, %1, %2, %0;" : "+l"(d) : "l"(a), "l"(b));
}

// -log(u), accurate near u->1 where __logf's absolute error would be amplified.
__device__ __forceinline__ float neg_log_u(float u) {
    float v = 1.0f - u;
    if (v < 0.0078125f)
        return v*(1.0f + v*(0.5f + v*(1.0f/3.0f)));
    return -__logf(u);
}

// epilogue for one (row, feature): logits in l1..l7 (l0 = 0 implicit)
__device__ __forceinline__ void cat_epilogue(
    const float* __restrict__ lg,        // 7 logits
    float4 G0, float4 G1,                // gumbel 8
    float4 D0, float4 D1,                // data_cat 8
    float missf, float& lp_out, float& samp_out)
{
    float lpi[8];
    lpi[0] = 0.0f;
    #pragma unroll
    for (int k = 1; k < 8; k++) lpi[k] = lg[k-1];
    float m = lpi[0];
    #pragma unroll
    for (int k = 1; k < 8; k++) m = fmaxf(m, lpi[k]);
    float se = 0.0f;
    #pragma unroll
    for (int k = 0; k < 8; k++) se += __expf(lpi[k] - m);
    float lse = m + __logf(se);

    float lp = D0.x*(lpi[0]-lse) + D0.y*(lpi[1]-lse) + D0.z*(lpi[2]-lse) + D0.w*(lpi[3]-lse)
             + D1.x*(lpi[4]-lse) + D1.y*(lpi[5]-lse) + D1.z*(lpi[6]-lse) + D1.w*(lpi[7]-lse);
    lp_out += lp * missf;

    float uv[8] = {G0.x,G0.y,G0.z,G0.w,G1.x,G1.y,G1.z,G1.w};
    float best = -1e30f; int bi = 0;
    #pragma unroll
    for (int k = 0; k < 8; k++) {
        float u  = fminf(fmaxf(uv[k], 1e-6f), 1.0f - 1e-6f);
        float gk = -__logf(neg_log_u(u));
        float val = lpi[k] + gk;
        if (val > best) { best = val; bi = k; }
    }
    samp_out = (float)bi;
}

__global__ __launch_bounds__(NTHREADS, 3)
void hivae_kernel(const float* __restrict__ y,   const float* __restrict__ s,
                  const float* __restrict__ st,  const float* __restrict__ bz,
                  const float* __restrict__ br,  const float* __restrict__ eps,
                  const float* __restrict__ gum, const int* __restrict__ miss,
                  float* __restrict__ out)
{
    extern __shared__ float sm[];
    char* smc = (char*)sm + MISS_BYTE_OFF;
    const int tid = threadIdx.x;
    const int rb  = blockIdx.x * ROWS;
    const int warp = tid >> 5, lane = tid & 31;
    const long B64 = (long)B_TOT*64;

    // ---------------- stage everything up front ----------------------------
    for (int idx = tid; idx < ROWS*DIN; idx += NTHREADS) {
        int row = idx >> 7, c = idx & 127;
        float v = (c < 64) ? y[(rb+row)*64 + c] : s[(rb+row)*64 + (c-64)];
        sm[YS_OFF + c*65 + row] = v;
    }
    for (int idx = tid; idx < ROWS*32; idx += NTHREADS) {
        int row = idx >> 5, c = idx & 31;
        sm[ST2_OFF  + c*65 + row] = st[(rb+row)*288 + c];
        sm[EPS2_OFF + c*65 + row] = eps[(rb+row)*32 + c];
    }
    for (int idx = tid; idx < ROWS*64; idx += NTHREADS) {
        int row = idx >> 6, c = idx & 63;
        smc[c*68 + row] = (char)miss[(rb+row)*64 + c];
    }
    if (tid < ROWS) sm[LP_OFF + tid] = 0.0f;
    __syncthreads();

    float lp_r[2] = {0.f, 0.f};   // this thread's rows: lane, lane+32

    // ========== categorical: 4 light passes (jj x row-half), no syncs ======
    #pragma unroll 1
    for (int pass = 0; pass < 4; pass++) {
        const int jj = pass >> 1, h = pass & 1;
        const int fp = jj*8 + warp;          // feature pair -> features 2fp, 2fp+1
        const int r  = h*32 + lane;
        const long grow = rb + r;

        // prefetch epilogue data BEFORE the d-loop (latency hidden by GEMV)
        const float4* gup = (const float4*)(gum + grow*256 + fp*16);
        float4 G0 = gup[0], G1 = gup[1], G2 = gup[2], G3 = gup[3];
        const float4* dcp = (const float4*)(st + grow*288 + 32 + fp*16);
        float4 D0 = dcp[0], D1 = dcp[1], D2 = dcp[2], D3 = dcp[3];

        u64 acc[7];
        {
            const float2* bp = &g_bc2[fp*8];
            #pragma unroll
            for (int o = 0; o < 7; o++) { float2 b = bp[o]; acc[o] = pack2(b.x, b.y); }
        }
        #pragma unroll 4
        for (int d = 0; d < DIN; d++) {
            float a = sm[YS_OFF + d*65 + r];
            u64 A = pack2(a, a);
            const ulonglong2* wp = (const ulonglong2*)&g_Wc2[(d*16 + fp)*4];
            ulonglong2 w0 = wp[0], w1 = wp[1], w2 = wp[2];
            u64 w6 = *(const u64*)(wp + 3);
            fma2(acc[0], A, w0.x); fma2(acc[1], A, w0.y);
            fma2(acc[2], A, w1.x); fma2(acc[3], A, w1.y);
            fma2(acc[4], A, w2.x); fma2(acc[5], A, w2.y);
            fma2(acc[6], A, w6);
        }

        float lg0[7], lg1[7];
        #pragma unroll
        for (int o = 0; o < 7; o++) { float2 v = unpack2(acc[o]); lg0[o] = v.x; lg1[o] = v.y; }

        float s0, s1;
        cat_epilogue(lg0, G0, G1, D0, D1, (float)smc[(32+2*fp)*68 + r], lp_r[h], s0);
        cat_epilogue(lg1, G2, G3, D2, D3, (float)smc[(33+2*fp)*68 + r], lp_r[h], s1);
        *(float2*)&out[grow*64 + 32 + 2*fp] = make_float2(s0, s1);
    }

    // =========== real: 4 features x 2 rows, (mean,logvar) packed ===========
    {
        const int f0 = warp*4;
        u64 ar[2][4];
        {
            float4 b0 = *(const float4*)&br[f0*2];
            float4 b1 = *(const float4*)&br[f0*2 + 4];
            ar[0][0] = ar[1][0] = pack2(b0.x, b0.y);
            ar[0][1] = ar[1][1] = pack2(b0.z, b0.w);
            ar[0][2] = ar[1][2] = pack2(b1.x, b1.y);
            ar[0][3] = ar[1][3] = pack2(b1.z, b1.w);
        }
        #pragma unroll 4
        for (int d = 0; d < DIN; d++) {
            float a0 = sm[YS_OFF + d*65 + lane];
            float a1 = sm[YS_OFF + d*65 + lane + 32];
            u64 A0 = pack2(a0, a0), A1 = pack2(a1, a1);
            ulonglong2 wA = *(const ulonglong2*)&g_Wr2[d*32 + f0];
            ulonglong2 wB = *(const ulonglong2*)&g_Wr2[d*32 + f0 + 2];
            fma2(ar[0][0], A0, wA.x); fma2(ar[1][0], A1, wA.x);
            fma2(ar[0][1], A0, wA.y); fma2(ar[1][1], A1, wA.y);
            fma2(ar[0][2], A0, wB.x); fma2(ar[1][2], A1, wB.x);
            fma2(ar[0][3], A0, wB.y); fma2(ar[1][3], A1, wB.y);
        }
        #pragma unroll
        for (int i = 0; i < 2; i++) {
            const int r = i*32 + lane;
            const long grow = rb + r;
            float samp[4];
            #pragma unroll
            for (int qf = 0; qf < 4; qf++) {
                const int f = f0 + qf;
                float2 mv = unpack2(ar[i][qf]);
                float mu = mv.x;
                float lv = fminf(fmaxf(mv.y, -10.0f), 10.0f);
                float x  = sm[ST2_OFF + f*65 + r];
                float mi = (float)smc[f*68 + r];
                float dmu = x - mu;
                lp_r[i] += (-0.5f*dmu*dmu*__expf(-lv) - 0.5f*lv - HALF_LOG2PI) * mi;
                float sd = fmaxf(__expf(0.5f*lv), 1e-6f);
                samp[qf] = mu + sd * sm[EPS2_OFF + f*65 + r];
            }
            *(float4*)&out[grow*64 + f0] = make_float4(samp[0], samp[1], samp[2], samp[3]);
        }
    }
    atomicAdd(&sm[LP_OFF + lane],      lp_r[0]);
    atomicAdd(&sm[LP_OFF + lane + 32], lp_r[1]);

    // =========== mean_pz: 8 z-outputs x 2 rows, z-pairs packed =============
    {
        const int zb = warp*8;
        u64 az[2][4];
        {
            float4 b0 = *(const float4*)&bz[zb];
            float4 b1 = *(const float4*)&bz[zb + 4];
            az[0][0] = az[1][0] = pack2(b0.x, b0.y);
            az[0][1] = az[1][1] = pack2(b0.z, b0.w);
            az[0][2] = az[1][2] = pack2(b1.x, b1.y);
            az[0][3] = az[1][3] = pack2(b1.z, b1.w);
        }
        #pragma unroll 4
        for (int d = 0; d < SDIM; d++) {
            float a0 = sm[YS_OFF + (64+d)*65 + lane];
            float a1 = sm[YS_OFF + (64+d)*65 + lane + 32];
            u64 A0 = pack2(a0, a0), A1 = pack2(a1, a1);
            ulonglong2 w0 = *(const ulonglong2*)&g_Wzt[d*64 + zb];
            ulonglong2 w1 = *(const ulonglong2*)&g_Wzt[d*64 + zb + 4];
            fma2(az[0][0], A0, w0.x); fma2(az[1][0], A1, w0.x);
            fma2(az[0][1], A0, w0.y); fma2(az[1][1], A1, w0.y);
            fma2(az[0][2], A0, w1.x); fma2(az[1][2], A1, w1.x);
            fma2(az[0][3], A0, w1.y); fma2(az[1][3], A1, w1.y);
        }
        #pragma unroll
        for (int i = 0; i < 2; i++) {
            const long grow = rb + i*32 + lane;
            float2 p0 = unpack2(az[i][0]), p1 = unpack2(az[i][1]);
            float2 p2 = unpack2(az[i][2]), p3 = unpack2(az[i][3]);
            *(float4*)&out[B64 + grow*64 + zb]     = make_float4(p0.x, p0.y, p1.x, p1.y);
            *(float4*)&out[B64 + grow*64 + zb + 4] = make_float4(p2.x, p2.y, p3.x, p3.y);
        }
    }

    // -------- zeros (log_var_pz), coalesced --------------------------------
    {
        const float4 z4 = make_float4(0.f,0.f,0.f,0.f);
        for (int idx = tid; idx < ROWS*16; idx += NTHREADS) {
            int row = idx >> 4, c = (idx & 15)*4;
            *(float4*)&out[2*B64 + (long)(rb+row)*64 + c] = z4;
        }
    }

    __syncthreads();
    if (tid < ROWS) out[3*B64 + rb + tid] = sm[LP_OFF + tid];
}

extern "C" void kernel_launch(void* const* d_in, const int* in_sizes, int n_in,
                              void* d_out, int out_size)
{
    const float* y    = (const float*)d_in[0];
    const float* s    = (const float*)d_in[1];
    const float* st   = (const float*)d_in[2];
    const float* Wz   = (const float*)d_in[3];
    const float* bz   = (const float*)d_in[4];
    const float* Wr   = (const float*)d_in[5];
    const float* br   = (const float*)d_in[6];
    const float* Wc   = (const float*)d_in[7];
    const float* bc   = (const float*)d_in[8];
    const float* eps  = (const float*)d_in[9];
    const float* gum  = (const float*)d_in[10];
    const int*   miss = (const int*)d_in[11];
    float* out = (float*)d_out;

    cudaFuncSetAttribute(hivae_kernel,
                         cudaFuncAttributeMaxDynamicSharedMemorySize, SMEM_BYTES);
    repack_kernel<<<16, 256>>>(Wc, Wr, Wz, bc);
    hivae_kernel<<<B_TOT/ROWS, NTHREADS, SMEM_BYTES>>>(
        y, s, st, bz, br, eps, gum, miss, out);
}

// round 6
// speedup vs baseline: 1.3318x; 1.3318x over previous
#include <cuda_runtime.h>

#define B_TOT    131072
#define DIN      128
#define SDIM     64
#define ROWS     128
#define NTHREADS 256
#define PAD      129
#define HALF_LOG2PI 0.9189385332046727f

// smem float offsets
#define YS_OFF   0                        // 128*129 = 16512 floats (66048 B)
#define ST2_OFF  0                        // overlay on YS after GEMVs: 32*129
#define EPS2_OFF (32*PAD)                 // 4128..8256 (inside YS region)
#define LP_OFF   (DIN*PAD)                // 16512, 128 floats
#define MISS_BYTE_OFF ((LP_OFF + ROWS)*4) // 66560
#define SMEM_BYTES (MISS_BYTE_OFF + 64*132)  // 75008 B -> 3 CTAs/SM

typedef unsigned long long u64;

// Repacked weights (prep kernel)
__device__ float4 g_Wc2[DIN*16*4];   // [d][fpair][8 f32x2: o0..o6,pad]
__device__ float2 g_Wr2[DIN*32];     // [d][f] (mean_w, logvar_w)
__device__ float  g_Wzt[SDIM*64];    // [d][z]
__device__ float2 g_bc2[16*8];       // cat bias pairs

__global__ void repack_kernel(const float* __restrict__ Wc,
                              const float* __restrict__ Wr,
                              const float* __restrict__ Wz,
                              const float* __restrict__ bc) {
    int idx = blockIdx.x*blockDim.x + threadIdx.x;
    if (idx < DIN*32) {
        int d = idx >> 5, f = idx & 31;
        g_Wr2[d*32 + f] = make_float2(Wr[(f*DIN + d)*2], Wr[(f*DIN + d)*2 + 1]);
        int dz = idx >> 6, z = idx & 63;
        g_Wzt[dz*64 + z] = Wz[z*SDIM + dz];
    }
    if (idx < DIN*16) {
        int d = idx >> 4, fp = idx & 15;
        const float* s0 = Wc + ((2*fp)*DIN + d)*7;
        const float* s1 = Wc + ((2*fp+1)*DIN + d)*7;
        float4* dst = &g_Wc2[(d*16 + fp)*4];
        dst[0] = make_float4(s0[0], s1[0], s0[1], s1[1]);
        dst[1] = make_float4(s0[2], s1[2], s0[3], s1[3]);
        dst[2] = make_float4(s0[4], s1[4], s0[5], s1[5]);
        dst[3] = make_float4(s0[6], s1[6], 0.0f, 0.0f);
    }
    if (idx < 128) {
        int fp = idx >> 3, o = idx & 7;
        g_bc2[idx] = (o < 7) ? make_float2(bc[(2*fp)*7 + o], bc[(2*fp+1)*7 + o])
                             : make_float2(0.0f, 0.0f);
    }
}

__device__ __forceinline__ u64 pack2(float lo, float hi) {
    u64 r; asm("mov.b64 %0, {%1, %2};" : "=l"(r) : "f"(lo), "f"(hi)); return r;
}
__device__ __forceinline__ float2 unpack2(u64 v) {
    float2 r; asm("mov.b64 {%0, %1}, %2;" : "=f"(r.x), "=f"(r.y) : "l"(v)); return r;
}
__device__ __forceinline__ void fma2(u64 &d, u64 a, u64 b) {
    asm("fma.rn.f32x2 %0, %1, %2, %0;" : "+l"(d) : "l"(a), "l"(b));
}

// -log(u), accurate near u->1 where __logf's absolute error would be amplified.
__device__ __forceinline__ float neg_log_u(float u) {
    float v = 1.0f - u;
    if (v < 0.0078125f)
        return v*(1.0f + v*(0.5f + v*(1.0f/3.0f)));
    return -__logf(u);
}

// epilogue for one (row, feature): 7 logits (l0 = 0 implicit)
__device__ __forceinline__ void cat_epilogue(
    const float* __restrict__ lg,
    float4 G0, float4 G1, float4 D0, float4 D1,
    float missf, float& lp_out, float& samp_out)
{
    float lpi[8];
    lpi[0] = 0.0f;
    #pragma unroll
    for (int k = 1; k < 8; k++) lpi[k] = lg[k-1];
    float m = lpi[0];
    #pragma unroll
    for (int k = 1; k < 8; k++) m = fmaxf(m, lpi[k]);
    float se = 0.0f;
    #pragma unroll
    for (int k = 0; k < 8; k++) se += __expf(lpi[k] - m);
    float lse = m + __logf(se);

    float lp = D0.x*(lpi[0]-lse) + D0.y*(lpi[1]-lse) + D0.z*(lpi[2]-lse) + D0.w*(lpi[3]-lse)
             + D1.x*(lpi[4]-lse) + D1.y*(lpi[5]-lse) + D1.z*(lpi[6]-lse) + D1.w*(lpi[7]-lse);
    lp_out += lp * missf;

    float uv[8] = {G0.x,G0.y,G0.z,G0.w,G1.x,G1.y,G1.z,G1.w};
    float best = -1e30f; int bi = 0;
    #pragma unroll
    for (int k = 0; k < 8; k++) {
        float u  = fminf(fmaxf(uv[k], 1e-6f), 1.0f - 1e-6f);
        float gk = -__logf(neg_log_u(u));
        float val = lpi[k] + gk;
        if (val > best) { best = val; bi = k; }
    }
    samp_out = (float)bi;
}

__global__ __launch_bounds__(NTHREADS, 3)
void hivae_kernel(const float* __restrict__ y,   const float* __restrict__ s,
                  const float* __restrict__ st,  const float* __restrict__ bz,
                  const float* __restrict__ br,  const float* __restrict__ eps,
                  const float* __restrict__ gum, const int* __restrict__ miss,
                  float* __restrict__ out)
{
    extern __shared__ float sm[];
    char* smc = (char*)sm + MISS_BYTE_OFF;
    const int tid = threadIdx.x;
    const int rb  = blockIdx.x * ROWS;
    const int warp = tid >> 5, lane = tid & 31;
    const long B64 = (long)B_TOT*64;

    // ---------------- stage YS (transposed) + miss bytes --------------------
    for (int idx = tid; idx < ROWS*DIN; idx += NTHREADS) {
        int row = idx >> 7, c = idx & 127;
        float v = (c < 64) ? y[(rb+row)*64 + c] : s[(rb+row)*64 + (c-64)];
        sm[YS_OFF + c*PAD + row] = v;
    }
    for (int idx = tid; idx < ROWS*64; idx += NTHREADS) {
        int row = idx >> 6, c = idx & 63;
        smc[c*132 + row] = (char)miss[(rb+row)*64 + c];
    }
    if (tid < ROWS) sm[LP_OFF + tid] = 0.0f;
    __syncthreads();

    float lp_r[4] = {0.f, 0.f, 0.f, 0.f};   // rows: lane + 32*i

    // ========== categorical: 4 rows per weight stream ======================
    #pragma unroll 1
    for (int jj = 0; jj < 2; jj++) {
        const int fp = jj*8 + warp;          // features 2fp, 2fp+1
        u64 acc[4][7];
        {
            const float2* bp = &g_bc2[fp*8];
            #pragma unroll
            for (int o = 0; o < 7; o++) {
                float2 b = bp[o];
                u64 v = pack2(b.x, b.y);
                acc[0][o] = v; acc[1][o] = v; acc[2][o] = v; acc[3][o] = v;
            }
        }
        #pragma unroll 2
        for (int d = 0; d < DIN; d++) {
            const ulonglong2* wp = (const ulonglong2*)&g_Wc2[(d*16 + fp)*4];
            ulonglong2 w0 = wp[0], w1 = wp[1], w2 = wp[2];
            u64 w6 = *(const u64*)(wp + 3);
            #pragma unroll
            for (int i = 0; i < 4; i++) {
                float a = sm[YS_OFF + d*PAD + lane + 32*i];
                u64 A = pack2(a, a);
                fma2(acc[i][0], A, w0.x); fma2(acc[i][1], A, w0.y);
                fma2(acc[i][2], A, w1.x); fma2(acc[i][3], A, w1.y);
                fma2(acc[i][4], A, w2.x); fma2(acc[i][5], A, w2.y);
                fma2(acc[i][6], A, w6);
            }
        }
        // epilogue, one row at a time (caps register pressure)
        #pragma unroll 1
        for (int i = 0; i < 4; i++) {
            const int r = lane + 32*i;
            const long grow = rb + r;
            float lg0[7], lg1[7];
            #pragma unroll
            for (int o = 0; o < 7; o++) {
                float2 v = unpack2(acc[i][o]); lg0[o] = v.x; lg1[o] = v.y;
            }
            const float4* gup = (const float4*)(gum + grow*256 + fp*16);
            const float4* dcp = (const float4*)(st + grow*288 + 32 + fp*16);
            float s0, s1;
            cat_epilogue(lg0, gup[0], gup[1], dcp[0], dcp[1],
                         (float)smc[(32+2*fp)*132 + r], lp_r[i], s0);
            cat_epilogue(lg1, gup[2], gup[3], dcp[2], dcp[3],
                         (float)smc[(33+2*fp)*132 + r], lp_r[i], s1);
            *(float2*)&out[grow*64 + 32 + 2*fp] = make_float2(s0, s1);
        }
    }

    // ========== mean_pz: 8 z-outputs x 4 rows, stores free the regs ========
    {
        const int zb = warp*8;
        u64 az[4][4];
        {
            float4 b0 = *(const float4*)&bz[zb];
            float4 b1 = *(const float4*)&bz[zb + 4];
            u64 v0 = pack2(b0.x, b0.y), v1 = pack2(b0.z, b0.w);
            u64 v2 = pack2(b1.x, b1.y), v3 = pack2(b1.z, b1.w);
            #pragma unroll
            for (int i = 0; i < 4; i++) {
                az[i][0] = v0; az[i][1] = v1; az[i][2] = v2; az[i][3] = v3;
            }
        }
        #pragma unroll 2
        for (int d = 0; d < SDIM; d++) {
            ulonglong2 w0 = *(const ulonglong2*)&g_Wzt[d*64 + zb];
            ulonglong2 w1 = *(const ulonglong2*)&g_Wzt[d*64 + zb + 4];
            #pragma unroll
            for (int i = 0; i < 4; i++) {
                float a = sm[YS_OFF + (64+d)*PAD + lane + 32*i];
                u64 A = pack2(a, a);
                fma2(az[i][0], A, w0.x); fma2(az[i][1], A, w0.y);
                fma2(az[i][2], A, w1.x); fma2(az[i][3], A, w1.y);
            }
        }
        #pragma unroll
        for (int i = 0; i < 4; i++) {
            const long grow = rb + lane + 32*i;
            float2 p0 = unpack2(az[i][0]), p1 = unpack2(az[i][1]);
            float2 p2 = unpack2(az[i][2]), p3 = unpack2(az[i][3]);
            *(float4*)&out[B64 + grow*64 + zb]     = make_float4(p0.x, p0.y, p1.x, p1.y);
            *(float4*)&out[B64 + grow*64 + zb + 4] = make_float4(p2.x, p2.y, p3.x, p3.y);
        }
    }

    // ========== real GEMV: 4 features x 4 rows =============================
    u64 ar[4][4];   // [row][feature], (mean, logvar) packed
    {
        const int f0 = warp*4;
        float4 b0 = *(const float4*)&br[f0*2];
        float4 b1 = *(const float4*)&br[f0*2 + 4];
        u64 v0 = pack2(b0.x, b0.y), v1 = pack2(b0.z, b0.w);
        u64 v2 = pack2(b1.x, b1.y), v3 = pack2(b1.z, b1.w);
        #pragma unroll
        for (int i = 0; i < 4; i++) {
            ar[i][0] = v0; ar[i][1] = v1; ar[i][2] = v2; ar[i][3] = v3;
        }
        #pragma unroll 2
        for (int d = 0; d < DIN; d++) {
            ulonglong2 wA = *(const ulonglong2*)&g_Wr2[d*32 + f0];
            ulonglong2 wB = *(const ulonglong2*)&g_Wr2[d*32 + f0 + 2];
            #pragma unroll
            for (int i = 0; i < 4; i++) {
                float a = sm[YS_OFF + d*PAD + lane + 32*i];
                u64 A = pack2(a, a);
                fma2(ar[i][0], A, wA.x); fma2(ar[i][1], A, wA.y);
                fma2(ar[i][2], A, wB.x); fma2(ar[i][3], A, wB.y);
            }
        }
    }

    // ---- all YS reads done: overlay st/eps into the YS region -------------
    __syncthreads();
    for (int idx = tid; idx < ROWS*32; idx += NTHREADS) {
        int row = idx >> 5, c = idx & 31;
        sm[ST2_OFF  + c*PAD + row] = st[(rb+row)*288 + c];
        sm[EPS2_OFF + c*PAD + row] = eps[(rb+row)*32 + c];
    }
    __syncthreads();

    // ========== real epilogue ==============================================
    {
        const int f0 = warp*4;
        #pragma unroll 1
        for (int i = 0; i < 4; i++) {
            const int r = lane + 32*i;
            const long grow = rb + r;
            float samp[4];
            #pragma unroll
            for (int qf = 0; qf < 4; qf++) {
                const int f = f0 + qf;
                float2 mv = unpack2(ar[i][qf]);
                float mu = mv.x;
                float lv = fminf(fmaxf(mv.y, -10.0f), 10.0f);
                float x  = sm[ST2_OFF + f*PAD + r];
                float mi = (float)smc[f*132 + r];
                float dmu = x - mu;
                lp_r[i] += (-0.5f*dmu*dmu*__expf(-lv) - 0.5f*lv - HALF_LOG2PI) * mi;
                float sd = fmaxf(__expf(0.5f*lv), 1e-6f);
                samp[qf] = mu + sd * sm[EPS2_OFF + f*PAD + r];
            }
            *(float4*)&out[grow*64 + f0] = make_float4(samp[0], samp[1], samp[2], samp[3]);
        }
    }

    // -------- log-p reduction + zeros ---------------------------------------
    #pragma unroll
    for (int i = 0; i < 4; i++)
        atomicAdd(&sm[LP_OFF + lane + 32*i], lp_r[i]);

    {
        const float4 z4 = make_float4(0.f,0.f,0.f,0.f);
        for (int idx = tid; idx < ROWS*16; idx += NTHREADS) {
            int row = idx >> 4, c = (idx & 15)*4;
            *(float4*)&out[2*B64 + (long)(rb+row)*64 + c] = z4;
        }
    }

    __syncthreads();
    if (tid < ROWS) out[3*B64 + rb + tid] = sm[LP_OFF + tid];
}

extern "C" void kernel_launch(void* const* d_in, const int* in_sizes, int n_in,
                              void* d_out, int out_size)
{
    const float* y    = (const float*)d_in[0];
    const float* s    = (const float*)d_in[1];
    const float* st   = (const float*)d_in[2];
    const float* Wz   = (const float*)d_in[3];
    const float* bz   = (const float*)d_in[4];
    const float* Wr   = (const float*)d_in[5];
    const float* br   = (const float*)d_in[6];
    const float* Wc   = (const float*)d_in[7];
    const float* bc   = (const float*)d_in[8];
    const float* eps  = (const float*)d_in[9];
    const float* gum  = (const float*)d_in[10];
    const int*   miss = (const int*)d_in[11];
    float* out = (float*)d_out;

    cudaFuncSetAttribute(hivae_kernel,
                         cudaFuncAttributeMaxDynamicSharedMemorySize, SMEM_BYTES);
    repack_kernel<<<16, 256>>>(Wc, Wr, Wz, bc);
    hivae_kernel<<<B_TOT/ROWS, NTHREADS, SMEM_BYTES>>>(
        y, s, st, bz, br, eps, gum, miss, out);
}

// round 7
// speedup vs baseline: 1.4439x; 1.0841x over previous
#include <cuda_runtime.h>

#define B_TOT    131072
#define DIN      128
#define SDIM     64
#define ROWS     128
#define NTHREADS 256
#define PAD      130
#define HALF_LOG2PI 0.9189385332046727f

// smem float offsets
#define YS_OFF   0                        // 128*130 = 16640 floats
#define ST2_OFF  0                        // overlay after GEMVs
#define EPS2_OFF (32*PAD)
#define LP_OFF   (DIN*PAD)                // 16640
#define MISS_BYTE_OFF ((LP_OFF + ROWS)*4) // 67072
#define SMEM_BYTES (MISS_BYTE_OFF + 64*PAD)  // 75392 B -> 3 CTAs/SM

typedef unsigned long long u64;

// Repacked weights (prep kernel)
__device__ float4 g_Wc2[DIN*16*4];   // [d][fpair][8 f32x2: o0..o6,pad]
__device__ float2 g_Wr2[DIN*32];     // [d][f] (mean_w, logvar_w)
__device__ float  g_Wzt[SDIM*64];    // [d][z]
__device__ float2 g_bc2[16*8];       // cat bias pairs

__global__ void repack_kernel(const float* __restrict__ Wc,
                              const float* __restrict__ Wr,
                              const float* __restrict__ Wz,
                              const float* __restrict__ bc) {
    int idx = blockIdx.x*blockDim.x + threadIdx.x;
    if (idx < DIN*32) {
        int d = idx >> 5, f = idx & 31;
        g_Wr2[d*32 + f] = make_float2(Wr[(f*DIN + d)*2], Wr[(f*DIN + d)*2 + 1]);
        int dz = idx >> 6, z = idx & 63;
        g_Wzt[dz*64 + z] = Wz[z*SDIM + dz];
    }
    if (idx < DIN*16) {
        int d = idx >> 4, fp = idx & 15;
        const float* s0 = Wc + ((2*fp)*DIN + d)*7;
        const float* s1 = Wc + ((2*fp+1)*DIN + d)*7;
        float4* dst = &g_Wc2[(d*16 + fp)*4];
        dst[0] = make_float4(s0[0], s1[0], s0[1], s1[1]);
        dst[1] = make_float4(s0[2], s1[2], s0[3], s1[3]);
        dst[2] = make_float4(s0[4], s1[4], s0[5], s1[5]);
        dst[3] = make_float4(s0[6], s1[6], 0.0f, 0.0f);
    }
    if (idx < 128) {
        int fp = idx >> 3, o = idx & 7;
        g_bc2[idx] = (o < 7) ? make_float2(bc[(2*fp)*7 + o], bc[(2*fp+1)*7 + o])
                             : make_float2(0.0f, 0.0f);
    }
}

__device__ __forceinline__ u64 pack2(float lo, float hi) {
    u64 r; asm("mov.b64 %0, {%1, %2};" : "=l"(r) : "f"(lo), "f"(hi)); return r;
}
__device__ __forceinline__ float2 unpack2(u64 v) {
    float2 r; asm("mov.b64 {%0, %1}, %2;" : "=f"(r.x), "=f"(r.y) : "l"(v)); return r;
}
__device__ __forceinline__ void fma2(u64 &d, u64 a, u64 b) {
    asm("fma.rn.f32x2 %0, %1, %2, %0;" : "+l"(d) : "l"(a), "l"(b));
}
// load a row-pair (rows 2l,2l+1) and duplicate each into a u64
__device__ __forceinline__ void ld_rowpair(const float* p, u64& Alo, u64& Ahi) {
    float2 f = *(const float2*)p;    // LDS.64, register pair
    Alo = pack2(f.x, f.x);
    Ahi = pack2(f.y, f.y);
}

// -log(u), accurate near u->1 where __logf's absolute error would be amplified.
__device__ __forceinline__ float neg_log_u(float u) {
    float v = 1.0f - u;
    if (v < 0.0078125f)
        return v*(1.0f + v*(0.5f + v*(1.0f/3.0f)));
    return -__logf(u);
}

// epilogue for one (row, feature): 7 logits (l0 = 0 implicit)
__device__ __forceinline__ void cat_epilogue(
    const float* __restrict__ lg,
    float4 G0, float4 G1, float4 D0, float4 D1,
    float missf, float& lp_out, float& samp_out)
{
    float lpi[8];
    lpi[0] = 0.0f;
    #pragma unroll
    for (int k = 1; k < 8; k++) lpi[k] = lg[k-1];
    float m = lpi[0];
    #pragma unroll
    for (int k = 1; k < 8; k++) m = fmaxf(m, lpi[k]);
    float se = 0.0f;
    #pragma unroll
    for (int k = 0; k < 8; k++) se += __expf(lpi[k] - m);
    float lse = m + __logf(se);

    float lp = D0.x*(lpi[0]-lse) + D0.y*(lpi[1]-lse) + D0.z*(lpi[2]-lse) + D0.w*(lpi[3]-lse)
             + D1.x*(lpi[4]-lse) + D1.y*(lpi[5]-lse) + D1.z*(lpi[6]-lse) + D1.w*(lpi[7]-lse);
    lp_out += lp * missf;

    float uv[8] = {G0.x,G0.y,G0.z,G0.w,G1.x,G1.y,G1.z,G1.w};
    float best = -1e30f; int bi = 0;
    #pragma unroll
    for (int k = 0; k < 8; k++) {
        float u  = fminf(fmaxf(uv[k], 1e-6f), 1.0f - 1e-6f);
        float gk = -__logf(neg_log_u(u));
        float val = lpi[k] + gk;
        if (val > best) { best = val; bi = k; }
    }
    samp_out = (float)bi;
}

__global__ __launch_bounds__(NTHREADS, 3)
void hivae_kernel(const float* __restrict__ y,   const float* __restrict__ s,
                  const float* __restrict__ st,  const float* __restrict__ bz,
                  const float* __restrict__ br,  const float* __restrict__ eps,
                  const float* __restrict__ gum, const int* __restrict__ miss,
                  float* __restrict__ out)
{
    extern __shared__ float sm[];
    char* smc = (char*)sm + MISS_BYTE_OFF;
    const int tid = threadIdx.x;
    const int rb  = blockIdx.x * ROWS;
    const int warp = tid >> 5, lane = tid & 31;
    const long B64 = (long)B_TOT*64;

    // thread's 4 rows: 2l, 2l+1, 64+2l, 64+2l+1
    int R[4];
    R[0] = 2*lane; R[1] = 2*lane + 1; R[2] = 64 + 2*lane; R[3] = 64 + 2*lane + 1;

    // ---------------- stage YS (transposed) + miss bytes --------------------
    for (int idx = tid; idx < ROWS*DIN; idx += NTHREADS) {
        int row = idx >> 7, c = idx & 127;
        float v = (c < 64) ? y[(rb+row)*64 + c] : s[(rb+row)*64 + (c-64)];
        sm[YS_OFF + c*PAD + row] = v;
    }
    for (int idx = tid; idx < ROWS*64; idx += NTHREADS) {
        int row = idx >> 6, c = idx & 63;
        smc[c*PAD + row] = (char)miss[(rb+row)*64 + c];
    }
    if (tid < ROWS) sm[LP_OFF + tid] = 0.0f;
    __syncthreads();

    float lp_r[4] = {0.f, 0.f, 0.f, 0.f};

    // ========== categorical: 4 rows per weight stream ======================
    #pragma unroll 1
    for (int jj = 0; jj < 2; jj++) {
        const int fp = jj*8 + warp;          // features 2fp, 2fp+1
        u64 acc[4][7];
        {
            const float2* bp = &g_bc2[fp*8];
            #pragma unroll
            for (int o = 0; o < 7; o++) {
                float2 b = bp[o];
                u64 v = pack2(b.x, b.y);
                acc[0][o] = v; acc[1][o] = v; acc[2][o] = v; acc[3][o] = v;
            }
        }
        #pragma unroll 4
        for (int d = 0; d < DIN; d++) {
            const ulonglong2* wp = (const ulonglong2*)&g_Wc2[(d*16 + fp)*4];
            ulonglong2 w0 = wp[0], w1 = wp[1], w2 = wp[2];
            u64 w6 = *(const u64*)(wp + 3);
            u64 A[4];
            ld_rowpair(&sm[YS_OFF + d*PAD + 2*lane],      A[0], A[1]);
            ld_rowpair(&sm[YS_OFF + d*PAD + 64 + 2*lane], A[2], A[3]);
            #pragma unroll
            for (int i = 0; i < 4; i++) {
                fma2(acc[i][0], A[i], w0.x); fma2(acc[i][1], A[i], w0.y);
                fma2(acc[i][2], A[i], w1.x); fma2(acc[i][3], A[i], w1.y);
                fma2(acc[i][4], A[i], w2.x); fma2(acc[i][5], A[i], w2.y);
                fma2(acc[i][6], A[i], w6);
            }
        }
        // epilogue, one row at a time; batch the 8 scattered LDG.128 up front
        #pragma unroll 1
        for (int i = 0; i < 4; i++) {
            const int r = R[i];
            const long grow = rb + r;
            const float4* gup = (const float4*)(gum + grow*256 + fp*16);
            const float4* dcp = (const float4*)(st + grow*288 + 32 + fp*16);
            float4 G0 = gup[0], G1 = gup[1], G2 = gup[2], G3 = gup[3];
            float4 D0 = dcp[0], D1 = dcp[1], D2 = dcp[2], D3 = dcp[3];
            float lg0[7], lg1[7];
            #pragma unroll
            for (int o = 0; o < 7; o++) {
                float2 v = unpack2(acc[i][o]); lg0[o] = v.x; lg1[o] = v.y;
            }
            float s0, s1;
            cat_epilogue(lg0, G0, G1, D0, D1,
                         (float)smc[(32+2*fp)*PAD + r], lp_r[i], s0);
            cat_epilogue(lg1, G2, G3, D2, D3,
                         (float)smc[(33+2*fp)*PAD + r], lp_r[i], s1);
            *(float2*)&out[grow*64 + 32 + 2*fp] = make_float2(s0, s1);
        }
    }

    // ========== mean_pz: 8 z-outputs x 4 rows ==============================
    {
        const int zb = warp*8;
        u64 az[4][4];
        {
            float4 b0 = *(const float4*)&bz[zb];
            float4 b1 = *(const float4*)&bz[zb + 4];
            u64 v0 = pack2(b0.x, b0.y), v1 = pack2(b0.z, b0.w);
            u64 v2 = pack2(b1.x, b1.y), v3 = pack2(b1.z, b1.w);
            #pragma unroll
            for (int i = 0; i < 4; i++) {
                az[i][0] = v0; az[i][1] = v1; az[i][2] = v2; az[i][3] = v3;
            }
        }
        #pragma unroll 4
        for (int d = 0; d < SDIM; d++) {
            ulonglong2 w0 = *(const ulonglong2*)&g_Wzt[d*64 + zb];
            ulonglong2 w1 = *(const ulonglong2*)&g_Wzt[d*64 + zb + 4];
            u64 A[4];
            ld_rowpair(&sm[YS_OFF + (64+d)*PAD + 2*lane],      A[0], A[1]);
            ld_rowpair(&sm[YS_OFF + (64+d)*PAD + 64 + 2*lane], A[2], A[3]);
            #pragma unroll
            for (int i = 0; i < 4; i++) {
                fma2(az[i][0], A[i], w0.x); fma2(az[i][1], A[i], w0.y);
                fma2(az[i][2], A[i], w1.x); fma2(az[i][3], A[i], w1.y);
            }
        }
        #pragma unroll
        for (int i = 0; i < 4; i++) {
            const long grow = rb + R[i];
            float2 p0 = unpack2(az[i][0]), p1 = unpack2(az[i][1]);
            float2 p2 = unpack2(az[i][2]), p3 = unpack2(az[i][3]);
            *(float4*)&out[B64 + grow*64 + zb]     = make_float4(p0.x, p0.y, p1.x, p1.y);
            *(float4*)&out[B64 + grow*64 + zb + 4] = make_float4(p2.x, p2.y, p3.x, p3.y);
        }
    }

    // ========== real GEMV: 4 features x 4 rows =============================
    u64 ar[4][4];   // [row][feature], (mean, logvar) packed
    {
        const int f0 = warp*4;
        float4 b0 = *(const float4*)&br[f0*2];
        float4 b1 = *(const float4*)&br[f0*2 + 4];
        u64 v0 = pack2(b0.x, b0.y), v1 = pack2(b0.z, b0.w);
        u64 v2 = pack2(b1.x, b1.y), v3 = pack2(b1.z, b1.w);
        #pragma unroll
        for (int i = 0; i < 4; i++) {
            ar[i][0] = v0; ar[i][1] = v1; ar[i][2] = v2; ar[i][3] = v3;
        }
        #pragma unroll 4
        for (int d = 0; d < DIN; d++) {
            ulonglong2 wA = *(const ulonglong2*)&g_Wr2[d*32 + f0];
            ulonglong2 wB = *(const ulonglong2*)&g_Wr2[d*32 + f0 + 2];
            u64 A[4];
            ld_rowpair(&sm[YS_OFF + d*PAD + 2*lane],      A[0], A[1]);
            ld_rowpair(&sm[YS_OFF + d*PAD + 64 + 2*lane], A[2], A[3]);
            #pragma unroll
            for (int i = 0; i < 4; i++) {
                fma2(ar[i][0], A[i], wA.x); fma2(ar[i][1], A[i], wA.y);
                fma2(ar[i][2], A[i], wB.x); fma2(ar[i][3], A[i], wB.y);
            }
        }
    }

    // ---- all YS reads done: overlay st/eps into the YS region -------------
    __syncthreads();
    for (int idx = tid; idx < ROWS*32; idx += NTHREADS) {
        int row = idx >> 5, c = idx & 31;
        sm[ST2_OFF  + c*PAD + row] = st[(rb+row)*288 + c];
        sm[EPS2_OFF + c*PAD + row] = eps[(rb+row)*32 + c];
    }
    __syncthreads();

    // ========== real epilogue ==============================================
    {
        const int f0 = warp*4;
        #pragma unroll 1
        for (int i = 0; i < 4; i++) {
            const int r = R[i];
            const long grow = rb + r;
            float samp[4];
            #pragma unroll
            for (int qf = 0; qf < 4; qf++) {
                const int f = f0 + qf;
                float2 mv = unpack2(ar[i][qf]);
                float mu = mv.x;
                float lv = fminf(fmaxf(mv.y, -10.0f), 10.0f);
                float x  = sm[ST2_OFF + f*PAD + r];
                float mi = (float)smc[f*PAD + r];
                float dmu = x - mu;
                lp_r[i] += (-0.5f*dmu*dmu*__expf(-lv) - 0.5f*lv - HALF_LOG2PI) * mi;
                float sd = fmaxf(__expf(0.5f*lv), 1e-6f);
                samp[qf] = mu + sd * sm[EPS2_OFF + f*PAD + r];
            }
            *(float4*)&out[grow*64 + f0] = make_float4(samp[0], samp[1], samp[2], samp[3]);
        }
    }

    // -------- log-p reduction + zeros ---------------------------------------
    #pragma unroll
    for (int i = 0; i < 4; i++)
        atomicAdd(&sm[LP_OFF + R[i]], lp_r[i]);

    {
        const float4 z4 = make_float4(0.f,0.f,0.f,0.f);
        for (int idx = tid; idx < ROWS*16; idx += NTHREADS) {
            int row = idx >> 4, c = (idx & 15)*4;
            *(float4*)&out[2*B64 + (long)(rb+row)*64 + c] = z4;
        }
    }

    __syncthreads();
    if (tid < ROWS) out[3*B64 + rb + tid] = sm[LP_OFF + tid];
}

extern "C" void kernel_launch(void* const* d_in, const int* in_sizes, int n_in,
                              void* d_out, int out_size)
{
    const float* y    = (const float*)d_in[0];
    const float* s    = (const float*)d_in[1];
    const float* st   = (const float*)d_in[2];
    const float* Wz   = (const float*)d_in[3];
    const float* bz   = (const float*)d_in[4];
    const float* Wr   = (const float*)d_in[5];
    const float* br   = (const float*)d_in[6];
    const float* Wc   = (const float*)d_in[7];
    const float* bc   = (const float*)d_in[8];
    const float* eps  = (const float*)d_in[9];
    const float* gum  = (const float*)d_in[10];
    const int*   miss = (const int*)d_in[11];
    float* out = (float*)d_out;

    cudaFuncSetAttribute(hivae_kernel,
                         cudaFuncAttributeMaxDynamicSharedMemorySize, SMEM_BYTES);
    repack_kernel<<<16, 256>>>(Wc, Wr, Wz, bc);
    hivae_kernel<<<B_TOT/ROWS, NTHREADS, SMEM_BYTES>>>(
        y, s, st, bz, br, eps, gum, miss, out);
}